// round 9
// baseline (speedup 1.0000x reference)
#include <cuda_runtime.h>
#include <cstdint>

// ---------------------------------------------------------------------------
// s[b,c] = sum_{i,u} W[i,c,u] * x[b,u,i]; out = squash(s)
// GEMM: D[M=1024 c][N=32 b] = A[c,k] B[k,b], k = i*16+u, K = 32768
// mma.sync.m16n8k8 tf32 + cp.async 5-stage pipeline, 2 CTAs/SM.
// ---------------------------------------------------------------------------

#define NB      32
#define NCOL    1024
#define USIZE   64
#define NUNITS  16
#define KS      32        // K-splits (grid.y): 64 i's per CTA
#define CBLK    8         // column blocks of 128 (grid.x)
#define STG     32        // K-stages per CTA; stage = 2 i's = 32 k
#define NS      5         // pipeline depth (smem buffers)

// per-stage smem: A raw fp32 16KB | B frag-ready tf32 4KB
#define BUF_BYTES  20480
#define SM_B_OFF   16384
#define SMEM_TOTAL (NS * BUF_BYTES)     // 100 KB -> 2 CTAs/SM

// Scratch (static device globals; no runtime allocation)
__device__ float g_Bfrag[2048 * 512];        // 4 MB: [i][j], j=np*128+s*64+l*2+e
__device__ float g_partial[KS * NB * NCOL];  // 4 MB: [ks][b][c]

__device__ __forceinline__ uint32_t f2tf32(float v) {
    uint32_t r;
    asm("cvt.rna.tf32.f32 %0, %1;" : "=r"(r) : "f"(v));
    return r;
}
__device__ __forceinline__ uint32_t smem_u32(const void* p) {
    uint32_t a;
    asm("{ .reg .u64 t; cvta.to.shared.u64 t, %1; cvt.u32.u64 %0, t; }"
        : "=r"(a) : "l"(p));
    return a;
}
__device__ __forceinline__ void cpa16(uint32_t dst, const void* src) {
    asm volatile("cp.async.cg.shared.global [%0], [%1], 16;"
                 :: "r"(dst), "l"(src));
}
#define CP_COMMIT() asm volatile("cp.async.commit_group;" ::: "memory")
#define CP_WAIT(n)  asm volatile("cp.async.wait_group %0;" :: "n"(n) : "memory")

__device__ __forceinline__ void mma_tf32(float4& d,
                                         uint32_t a0, uint32_t a1,
                                         uint32_t a2, uint32_t a3,
                                         uint32_t b0, uint32_t b1) {
    asm volatile(
        "mma.sync.aligned.m16n8k8.row.col.f32.tf32.tf32.f32 "
        "{%0,%1,%2,%3}, {%4,%5,%6,%7}, {%8,%9}, {%0,%1,%2,%3};"
        : "+f"(d.x), "+f"(d.y), "+f"(d.z), "+f"(d.w)
        : "r"(a0), "r"(a1), "r"(a2), "r"(a3), "r"(b0), "r"(b1));
}

// ---------------------------------------------------------------------------
// Prep: x (B,U,IC) -> g_Bfrag[i][j] = tf32(x[b][u][i])
//   j = np*128 + 64 s + 2 l + e; b = 8 np + (l>>2); u = 4 (l&3) + 2 s + e
// 1 element per thread; grid = 128 i-tiles x 4 np x 8 g = 4096 blocks of 256.
// Reads 64B-coalesced, writes in 32B runs; 1KB smem transpose tile.
// ---------------------------------------------------------------------------
__global__ void __launch_bounds__(256) k_prep(const float* __restrict__ x) {
    __shared__ float t[16][17];
    const int bid = blockIdx.x;
    const int g   = bid & 7;
    const int np  = (bid >> 3) & 3;
    const int i0  = (bid >> 5) * 16;
    const int b   = 8 * np + g;
    const int tid = threadIdx.x;

    // read: 16 u-rows x 16 i's (each warp: 2 rows x 64B)
    {
        const int u = tid >> 4, iloc = tid & 15;
        t[u][iloc] = x[(size_t)b * 32768 + (size_t)u * 2048 + i0 + iloc];
    }
    __syncthreads();

    // write: for each of 16 i's, the 16 j's owned by this (np, g)
    {
        const int il2 = tid >> 4, m = tid & 15;
        const int w = m & 7, s = m >> 3;
        const int u = 4 * (w >> 1) + 2 * s + (w & 1);
        g_Bfrag[(size_t)(i0 + il2) * 512 + np * 128 + 64 * s + 8 * g + w] =
            __uint_as_float(f2tf32(t[u][il2]));
    }
}

// ---------------------------------------------------------------------------
// Main GEMM. grid (CBLK, KS), 256 thr = 8 warps; warp wr owns m-rows
// cb*128 + wr*16 .. +16. cp.async 5-stage ring; K = 1024 per CTA. 2 CTAs/SM.
// Next stage is issued BEFORE compute so loads fly under the MMA work.
// ---------------------------------------------------------------------------
__global__ void __launch_bounds__(256, 2) k_main(const float* __restrict__ W) {
    extern __shared__ char sm[];
    const int tid = threadIdx.x;
    const int wr = tid >> 5, l = tid & 31;
    const int g = l >> 2, t4 = l & 3;
    const int cb = blockIdx.x, ks = blockIdx.y;
    const int i00 = ks * 64;

    // issue stage st into ring buffer st%NS
    auto issue = [&](int st) {
        const int ib = i00 + st * 2;
        const uint32_t sa = smem_u32(sm + (st % NS) * BUF_BYTES);
#pragma unroll
        for (int r = 0; r < 4; ++r) {
            const int q = tid + 256 * r;           // 16B chunk id, 0..1023
            const int ii = q >> 9, qi = q & 511;
            cpa16(sa + q * 16,
                  W + (size_t)(ib + ii) * 16384 + cb * 2048 + qi * 4);
        }
        cpa16(sa + SM_B_OFF + tid * 16, g_Bfrag + (size_t)ib * 512 + tid * 4);
    };

#pragma unroll
    for (int st = 0; st < NS - 1; ++st) { issue(st); CP_COMMIT(); }

    float4 acc[4];
#pragma unroll
    for (int np = 0; np < 4; ++np) acc[np] = make_float4(0.f, 0.f, 0.f, 0.f);

    const int arow0 = (wr * 16 + g) * 4 + t4;        // 16B chunk within i-slab
    const int arow1 = (wr * 16 + 8 + g) * 4 + t4;

#pragma unroll 1
    for (int st = 0; st < STG; ++st) {
        CP_WAIT(NS - 2);
        __syncthreads();

        // issue stage st+NS-1 FIRST (barrier above proves buffer st-1 consumed)
        if (st + NS - 1 < STG) issue(st + NS - 1);
        CP_COMMIT();   // always commit to keep group accounting aligned

        char* const buf = sm + (st % NS) * BUF_BYTES;
#pragma unroll
        for (int ii = 0; ii < 2; ++ii) {
            uint4 r0 = *(const uint4*)(buf + (ii * 512 + arow0) * 16);
            uint4 r1 = *(const uint4*)(buf + (ii * 512 + arow1) * 16);
            uint32_t a[8];
            a[0] = f2tf32(__uint_as_float(r0.x));
            a[1] = f2tf32(__uint_as_float(r1.x));
            a[2] = f2tf32(__uint_as_float(r0.y));
            a[3] = f2tf32(__uint_as_float(r1.y));
            a[4] = f2tf32(__uint_as_float(r0.z));
            a[5] = f2tf32(__uint_as_float(r1.z));
            a[6] = f2tf32(__uint_as_float(r0.w));
            a[7] = f2tf32(__uint_as_float(r1.w));
#pragma unroll
            for (int s = 0; s < 2; ++s) {
                const uint32_t a0 = a[s * 4 + 0], a1 = a[s * 4 + 1];
                const uint32_t a2 = a[s * 4 + 2], a3 = a[s * 4 + 3];
#pragma unroll
                for (int np = 0; np < 4; ++np) {
                    float2 bb = *(const float2*)(buf + SM_B_OFF + ii * 2048 +
                                                 ((np * 2 + s) * 64 + l * 2) * 4);
                    mma_tf32(acc[np], a0, a1, a2, a3,
                             __float_as_uint(bb.x), __float_as_uint(bb.y));
                }
            }
        }
    }

    // epilogue: rows g/g+8 of m-tile, cols 2t4/2t4+1 of each n-tile
    const int c0 = cb * 128 + wr * 16 + g;
#pragma unroll
    for (int np = 0; np < 4; ++np) {
        const int b0 = np * 8 + 2 * t4;
        g_partial[((size_t)ks * 32 + b0)     * NCOL + c0]     = acc[np].x;
        g_partial[((size_t)ks * 32 + b0 + 1) * NCOL + c0]     = acc[np].y;
        g_partial[((size_t)ks * 32 + b0)     * NCOL + c0 + 8] = acc[np].z;
        g_partial[((size_t)ks * 32 + b0 + 1) * NCOL + c0 + 8] = acc[np].w;
    }
}

// ---------------------------------------------------------------------------
// Reduce K-splits + squash (fused). grid (32 b, 4 k-chunks), 256 threads.
// Each block: k in [kc*16, kc*16+16), all 16 j's -> 256 c's.
// ---------------------------------------------------------------------------
__global__ void __launch_bounds__(256) k_squash(float* __restrict__ out) {
    const int b = blockIdx.x, kc = blockIdx.y;
    const int tid = threadIdx.x;
    const int j = tid >> 4, k16 = tid & 15;
    const int k = kc * 16 + k16;
    const int c = j * USIZE + k;

    float s = 0.f;
#pragma unroll
    for (int ks = 0; ks < KS; ++ks)
        s += g_partial[((size_t)ks * 32 + b) * NCOL + c];

    __shared__ float sq[NUNITS][16];
    __shared__ float mag[16];
    sq[j][k16] = s * s;
    __syncthreads();
    if (tid < 16) {
        float m = 0.f;
#pragma unroll
        for (int jj = 0; jj < NUNITS; ++jj) m += sq[jj][tid];
        mag[tid] = m;
    }
    __syncthreads();
    const float m = mag[k16];
    out[b * NCOL + c] = s * m / ((1.0f + m) * sqrtf(m));
}

// ---------------------------------------------------------------------------
extern "C" void kernel_launch(void* const* d_in, const int* in_sizes, int n_in,
                              void* d_out, int out_size) {
    const float* x = (const float*)d_in[0];
    const float* W = (const float*)d_in[1];
    if (n_in >= 2 && in_sizes[0] > in_sizes[1]) {
        W = (const float*)d_in[0];
        x = (const float*)d_in[1];
    }
    float* out = (float*)d_out;

    static bool attr_set = false;
    if (!attr_set) {
        cudaFuncSetAttribute(k_main, cudaFuncAttributeMaxDynamicSharedMemorySize,
                             SMEM_TOTAL);
        attr_set = true;
    }

    k_prep<<<4096, 256>>>(x);
    dim3 gm(CBLK, KS);
    k_main<<<gm, 256, SMEM_TOTAL>>>(W);
    dim3 gs(NB, 4);
    k_squash<<<gs, 256>>>(out);
}

// round 10
// speedup vs baseline: 1.0540x; 1.0540x over previous
#include <cuda_runtime.h>
#include <cstdint>

// ---------------------------------------------------------------------------
// s[b,c] = sum_{i,u} W[i,c,u] * x[b,u,i]; out = squash(s)
// GEMM: D[M=1024 c][N=32 b] = A[c,k] B[k,b], k = i*16+u, K = 32768
// mma.sync.m16n8k8 tf32 + cp.async 5-stage pipeline, 2 CTAs/SM.
// ---------------------------------------------------------------------------

#define NB      32
#define NCOL    1024
#define USIZE   64
#define NUNITS  16
#define KS      32        // K-splits (grid.y): 64 i's per CTA
#define CBLK    8         // column blocks of 128 (grid.x)
#define STG     32        // K-stages per CTA; stage = 2 i's = 32 k
#define NS      5         // pipeline depth (smem buffers)

// per-stage smem: A raw fp32 16KB | B frag-ready tf32 4KB
#define BUF_BYTES  20480
#define SM_B_OFF   16384
#define SMEM_TOTAL (NS * BUF_BYTES)     // 100 KB -> 2 CTAs/SM

// Scratch (static device globals; no runtime allocation)
__device__ float g_Bfrag[2048 * 512];        // 4 MB: [i][j], j=np*128+s*64+2l+e
__device__ float g_partial[KS * NB * NCOL];  // 4 MB: [ks][b][c]

__device__ __forceinline__ uint32_t f2tf32(float v) {
    uint32_t r;
    asm("cvt.rna.tf32.f32 %0, %1;" : "=r"(r) : "f"(v));
    return r;
}
__device__ __forceinline__ uint32_t smem_u32(const void* p) {
    uint32_t a;
    asm("{ .reg .u64 t; cvta.to.shared.u64 t, %1; cvt.u32.u64 %0, t; }"
        : "=r"(a) : "l"(p));
    return a;
}
__device__ __forceinline__ void cpa16(uint32_t dst, const void* src) {
    asm volatile("cp.async.cg.shared.global [%0], [%1], 16;"
                 :: "r"(dst), "l"(src));
}
#define CP_COMMIT() asm volatile("cp.async.commit_group;" ::: "memory")
#define CP_WAIT(n)  asm volatile("cp.async.wait_group %0;" :: "n"(n) : "memory")

__device__ __forceinline__ void mma_tf32(float4& d,
                                         uint32_t a0, uint32_t a1,
                                         uint32_t a2, uint32_t a3,
                                         uint32_t b0, uint32_t b1) {
    asm volatile(
        "mma.sync.aligned.m16n8k8.row.col.f32.tf32.tf32.f32 "
        "{%0,%1,%2,%3}, {%4,%5,%6,%7}, {%8,%9}, {%0,%1,%2,%3};"
        : "+f"(d.x), "+f"(d.y), "+f"(d.z), "+f"(d.w)
        : "r"(a0), "r"(a1), "r"(a2), "r"(a3), "r"(b0), "r"(b1));
}

// ---------------------------------------------------------------------------
// Prep: x (B,U,IC) -> g_Bfrag[i][j] = tf32(x[b][u][i])
//   j = np*128 + 64 s + 2 l + e;  l = 4g+t;  b = 8 np + g;  u = 4 t + 2 s + e
// Block = (i-tile of 16) x (np, s). For fixed (np,s) the 64-j range is
// CONTIGUOUS -> writes are 16 runs of 256B, fully coalesced. Reads are 64
// (b,u)-rows x 64B, coalesced. grid = 128*8 = 1024 blocks, 4 elem/thread.
// ---------------------------------------------------------------------------
__global__ void __launch_bounds__(256) k_prep(const float* __restrict__ x) {
    __shared__ float t[64][17];             // row = g*8 + (t*2+e), col = iloc
    const int bid = blockIdx.x;
    const int s   = bid & 1;
    const int np  = (bid >> 1) & 3;
    const int i0  = (bid >> 3) * 16;
    const int tid = threadIdx.x;

    // read: 64 rows x 16 i's
#pragma unroll
    for (int it = 0; it < 4; ++it) {
        int idx = it * 256 + tid;           // 0..1023
        int iloc = idx & 15, r = idx >> 4;  // r = g*8 + q
        int g = r >> 3, q = r & 7;
        int u = 4 * (q >> 1) + 2 * s + (q & 1);
        t[r][iloc] = x[(size_t)(8 * np + g) * 32768 + (size_t)u * 2048 + i0 + iloc];
    }
    __syncthreads();

    // write: 16 i's x 64 contiguous j's
#pragma unroll
    for (int it = 0; it < 4; ++it) {
        int idx = it * 256 + tid;
        int jloc = idx & 63, iloc = idx >> 6;   // jloc = 8g + 2t + e
        int g = jloc >> 3, tt = (jloc >> 1) & 3, e = jloc & 1;
        g_Bfrag[(size_t)(i0 + iloc) * 512 + np * 128 + s * 64 + jloc] =
            __uint_as_float(f2tf32(t[g * 8 + tt * 2 + e][iloc]));
    }
}

// ---------------------------------------------------------------------------
// Main GEMM. grid (CBLK, KS), 256 thr = 8 warps; warp wr owns m-rows
// cb*128 + wr*16 .. +16. cp.async 5-stage ring; K = 1024 per CTA. 2 CTAs/SM.
// Next stage is issued BEFORE compute so loads fly under the MMA work.
// ---------------------------------------------------------------------------
__global__ void __launch_bounds__(256, 2) k_main(const float* __restrict__ W) {
    extern __shared__ char sm[];
    const int tid = threadIdx.x;
    const int wr = tid >> 5, l = tid & 31;
    const int g = l >> 2, t4 = l & 3;
    const int cb = blockIdx.x, ks = blockIdx.y;
    const int i00 = ks * 64;

    // issue stage st into ring buffer st%NS
    auto issue = [&](int st) {
        const int ib = i00 + st * 2;
        const uint32_t sa = smem_u32(sm + (st % NS) * BUF_BYTES);
#pragma unroll
        for (int r = 0; r < 4; ++r) {
            const int q = tid + 256 * r;           // 16B chunk id, 0..1023
            const int ii = q >> 9, qi = q & 511;
            cpa16(sa + q * 16,
                  W + (size_t)(ib + ii) * 16384 + cb * 2048 + qi * 4);
        }
        cpa16(sa + SM_B_OFF + tid * 16, g_Bfrag + (size_t)ib * 512 + tid * 4);
    };

#pragma unroll
    for (int st = 0; st < NS - 1; ++st) { issue(st); CP_COMMIT(); }

    float4 acc[4];
#pragma unroll
    for (int np = 0; np < 4; ++np) acc[np] = make_float4(0.f, 0.f, 0.f, 0.f);

    const int arow0 = (wr * 16 + g) * 4 + t4;        // 16B chunk within i-slab
    const int arow1 = (wr * 16 + 8 + g) * 4 + t4;

#pragma unroll 1
    for (int st = 0; st < STG; ++st) {
        CP_WAIT(NS - 2);
        __syncthreads();

        // issue stage st+NS-1 FIRST (barrier above proves buffer st-1 consumed)
        if (st + NS - 1 < STG) issue(st + NS - 1);
        CP_COMMIT();   // always commit to keep group accounting aligned

        char* const buf = sm + (st % NS) * BUF_BYTES;
#pragma unroll
        for (int ii = 0; ii < 2; ++ii) {
            uint4 r0 = *(const uint4*)(buf + (ii * 512 + arow0) * 16);
            uint4 r1 = *(const uint4*)(buf + (ii * 512 + arow1) * 16);
            uint32_t a[8];
            a[0] = f2tf32(__uint_as_float(r0.x));
            a[1] = f2tf32(__uint_as_float(r1.x));
            a[2] = f2tf32(__uint_as_float(r0.y));
            a[3] = f2tf32(__uint_as_float(r1.y));
            a[4] = f2tf32(__uint_as_float(r0.z));
            a[5] = f2tf32(__uint_as_float(r1.z));
            a[6] = f2tf32(__uint_as_float(r0.w));
            a[7] = f2tf32(__uint_as_float(r1.w));
#pragma unroll
            for (int s = 0; s < 2; ++s) {
                const uint32_t a0 = a[s * 4 + 0], a1 = a[s * 4 + 1];
                const uint32_t a2 = a[s * 4 + 2], a3 = a[s * 4 + 3];
#pragma unroll
                for (int np = 0; np < 4; ++np) {
                    float2 bb = *(const float2*)(buf + SM_B_OFF + ii * 2048 +
                                                 ((np * 2 + s) * 64 + l * 2) * 4);
                    mma_tf32(acc[np], a0, a1, a2, a3,
                             __float_as_uint(bb.x), __float_as_uint(bb.y));
                }
            }
        }
    }

    // epilogue: rows g/g+8 of m-tile, cols 2t4/2t4+1 of each n-tile
    const int c0 = cb * 128 + wr * 16 + g;
#pragma unroll
    for (int np = 0; np < 4; ++np) {
        const int b0 = np * 8 + 2 * t4;
        g_partial[((size_t)ks * 32 + b0)     * NCOL + c0]     = acc[np].x;
        g_partial[((size_t)ks * 32 + b0 + 1) * NCOL + c0]     = acc[np].y;
        g_partial[((size_t)ks * 32 + b0)     * NCOL + c0 + 8] = acc[np].z;
        g_partial[((size_t)ks * 32 + b0 + 1) * NCOL + c0 + 8] = acc[np].w;
    }
}

// ---------------------------------------------------------------------------
// Reduce K-splits + squash (fused). grid (32 b, 4 k-chunks), 256 threads.
// ---------------------------------------------------------------------------
__global__ void __launch_bounds__(256) k_squash(float* __restrict__ out) {
    const int b = blockIdx.x, kc = blockIdx.y;
    const int tid = threadIdx.x;
    const int j = tid >> 4, k16 = tid & 15;
    const int k = kc * 16 + k16;
    const int c = j * USIZE + k;

    float s = 0.f;
#pragma unroll
    for (int ks = 0; ks < KS; ++ks)
        s += g_partial[((size_t)ks * 32 + b) * NCOL + c];

    __shared__ float sq[NUNITS][16];
    __shared__ float mag[16];
    sq[j][k16] = s * s;
    __syncthreads();
    if (tid < 16) {
        float m = 0.f;
#pragma unroll
        for (int jj = 0; jj < NUNITS; ++jj) m += sq[jj][tid];
        mag[tid] = m;
    }
    __syncthreads();
    const float m = mag[k16];
    out[b * NCOL + c] = s * m / ((1.0f + m) * sqrtf(m));
}

// ---------------------------------------------------------------------------
extern "C" void kernel_launch(void* const* d_in, const int* in_sizes, int n_in,
                              void* d_out, int out_size) {
    const float* x = (const float*)d_in[0];
    const float* W = (const float*)d_in[1];
    if (n_in >= 2 && in_sizes[0] > in_sizes[1]) {
        W = (const float*)d_in[0];
        x = (const float*)d_in[1];
    }
    float* out = (float*)d_out;

    static bool attr_set = false;
    if (!attr_set) {
        cudaFuncSetAttribute(k_main, cudaFuncAttributeMaxDynamicSharedMemorySize,
                             SMEM_TOTAL);
        attr_set = true;
    }

    k_prep<<<1024, 256>>>(x);
    dim3 gm(CBLK, KS);
    k_main<<<gm, 256, SMEM_TOTAL>>>(W);
    dim3 gs(NB, 4);
    k_squash<<<gs, 256>>>(out);
}